// round 16
// baseline (speedup 1.0000x reference)
#include <cuda_runtime.h>
#include <cuda_fp16.h>
#include <cstdint>
#include <cstring>

// DynamicRouting: grouped 1x1 conv via single-pass fp16 mma.sync (fp32 accum).
// con lives in REGISTERS as packed half2 (hcon[8][8] per thread, ~2.4e-4 extra
// rounding). Routing epilogue: per-pixel Gram matrices, cross-warp exchange via
// 18KB smem. smem total 50KB (no con array).

#define G   8
#define FO  64
#define FI  64
#define HW  4096
#define C   512
#define BSZ 32
#define TP  64
#define NTHREADS 256

// smem: [sgram 2*64*36 floats = 18432 B][buf0 16KB][buf1 16KB]
#define OFF_BUF 18432
#define BUFSZ   16384                  // [A 8K | B 8K] fp16 tiles
#define AOF 0
#define BOF 8192
#define SMEM_TOTAL (OFF_BUF + 2*BUFSZ) // 51200 B

// packed weights: per group 8KB fp16, swizzled B-tile layout
__device__ __align__(16) unsigned char g_wpack[G * 8192];

__device__ __forceinline__ uint32_t swz(uint32_t off) {
    return off ^ ((off >> 3) & 0x70);
}
__device__ __forceinline__ uint32_t s2u(const void* p) {
    return (uint32_t)__cvta_generic_to_shared(p);
}
__device__ __forceinline__ void cp16(uint32_t d, const void* s) {
    asm volatile("cp.async.cg.shared.global [%0], [%1], 16;\n" :: "r"(d), "l"(s));
}
__device__ __forceinline__ void cp_commit() {
    asm volatile("cp.async.commit_group;\n");
}
template <int N>
__device__ __forceinline__ void cp_wait() {
    asm volatile("cp.async.wait_group %0;\n" :: "n"(N));
}
__device__ __forceinline__ uint32_t h2pack(float v0, float v1) {
    __half2 h = __floats2half2_rn(v0, v1);
    uint32_t r; memcpy(&r, &h, 4); return r;
}
__device__ __forceinline__ float2 h2unpack(uint32_t u) {
    __half2 h; memcpy(&h, &u, 4);
    return __half22float2(h);
}
__device__ __forceinline__ void mma16816(float* d,
    uint32_t a0, uint32_t a1, uint32_t a2, uint32_t a3, uint32_t b0, uint32_t b1)
{
    asm volatile("mma.sync.aligned.m16n8k16.row.col.f32.f16.f16.f32 "
        "{%0,%1,%2,%3}, {%4,%5,%6,%7}, {%8,%9}, {%0,%1,%2,%3};"
        : "+f"(d[0]), "+f"(d[1]), "+f"(d[2]), "+f"(d[3])
        : "r"(a0), "r"(a1), "r"(a2), "r"(a3), "r"(b0), "r"(b1));
}
__device__ __forceinline__ float sigmoidf(float b) {
    return 1.f / (1.f + __expf(-b));
}
__device__ __forceinline__ uint32_t lds32(const char* p) {
    return *(const uint32_t*)p;
}

// ---- pre-kernel: w fp32 [g][o][i] -> fp16 swizzled B tiles ----
__global__ void pack_w_kernel(const float* __restrict__ w) {
    int f = blockIdx.x * blockDim.x + threadIdx.x;   // 0..16383 (word pairs)
    int g = f >> 11, rem = f & 2047;
    int o = rem >> 5, iw = rem & 31;                 // i = 2*iw
    const float* src = w + (((size_t)g * FO + o) * FI + 2 * iw);
    uint32_t hv = h2pack(src[0], src[1]);
    uint32_t boff = swz((uint32_t)(o * 128 + iw * 4));
    *(uint32_t*)(g_wpack + g * 8192 + boff) = hv;
}

__global__ __launch_bounds__(NTHREADS, 1)
void dynrout_hmma(const float* __restrict__ x, const float* __restrict__ bias,
                  float* __restrict__ out)
{
    extern __shared__ char smem[];
    float* sgram = (float*)smem;            // [2][64][36]

    const int tid = threadIdx.x;
    const int wid = tid >> 5, lid = tid & 31;
    const int b   = blockIdx.x >> 6;
    const int p0  = (blockIdx.x & 63) << 6;

    // producer roles (all 256 threads)
    const int xpx = tid & 63;
    const int xi0 = (tid >> 6) << 4;

    // mma roles: 8 warps, m16 x n32 tiles
    const int gr = lid >> 2, tig = lid & 3;
    const int pb = (wid & 3) << 4;          // px tile base
    const int ob = (wid >> 2) << 5;         // o tile base (32 o's)
    const int slot = wid >> 2;              // o-half = gram slot

    const float* xbase = x + (size_t)b * C * HW + p0;
    float xr[16];

    auto ldx = [&](int g) {
        const float* xp = xbase + (size_t)g * FI * HW + xpx;
        #pragma unroll
        for (int k = 0; k < 16; k++) xr[k] = __ldg(xp + (size_t)(xi0 + k) * HW);
    };
    auto issueB = [&](int g, int buf) {      // 8KB coalesced fp16 tile
        const unsigned char* src = g_wpack + g * 8192;
        uint32_t d0 = s2u(smem + OFF_BUF + buf * BUFSZ + BOF);
        #pragma unroll
        for (int r = 0; r < 2; r++)
            cp16(d0 + (uint32_t)(r * 4096 + tid * 16), src + r * 4096 + tid * 16);
        cp_commit();
    };
    auto cvtA = [&](int buf) {
        char* bp = smem + OFF_BUF + buf * BUFSZ;
        uint32_t hv[8];
        #pragma unroll
        for (int k = 0; k < 8; k++) hv[k] = h2pack(xr[2*k], xr[2*k+1]);
        uint32_t offA = (uint32_t)(xpx * 128 + xi0 * 2);
        *(uint4*)(bp + AOF + swz(offA))    = make_uint4(hv[0], hv[1], hv[2], hv[3]);
        *(uint4*)(bp + AOF + swz(offA+16)) = make_uint4(hv[4], hv[5], hv[6], hv[7]);
    };

    // register-resident con: hcon[g][2*jj+p2] = half2(acc[jj][2*p2], acc[jj][2*p2+1])
    // element (g, jj, p2, kk): o = ob + 8*jj + 2*tig + kk, px = pb + gr + 8*p2
    uint32_t hcon[G][8];

    auto mma_group = [&](int g, uint32_t (&hc)[8]) {
        const char* bp = smem + OFF_BUF + (g & 1) * BUFSZ;
        float acc[4][4];
        #pragma unroll
        for (int j = 0; j < 4; j++)
            #pragma unroll
            for (int k = 0; k < 4; k++) acc[j][k] = 0.f;

        #pragma unroll
        for (int ks = 0; ks < 4; ks++) {
            uint32_t r0 = (uint32_t)((pb + gr)     * 128 + tig * 4 + ks * 32);
            uint32_t r1 = (uint32_t)((pb + gr + 8) * 128 + tig * 4 + ks * 32);
            uint32_t a0 = lds32(bp + AOF + swz(r0));
            uint32_t a1 = lds32(bp + AOF + swz(r1));
            uint32_t a2 = lds32(bp + AOF + swz(r0 + 16));
            uint32_t a3 = lds32(bp + AOF + swz(r1 + 16));
            #pragma unroll
            for (int jj = 0; jj < 4; jj++) {
                uint32_t rb = (uint32_t)((ob + 8 * jj + gr) * 128 + tig * 4 + ks * 32);
                uint32_t b0 = lds32(bp + BOF + swz(rb));
                uint32_t b1 = lds32(bp + BOF + swz(rb + 16));
                mma16816(acc[jj], a0, a1, a2, a3, b0, b1);
            }
        }
        // compress to half2 pairs (kk0, kk1) per (jj, p2)
        #pragma unroll
        for (int jj = 0; jj < 4; jj++) {
            hc[2 * jj]     = h2pack(acc[jj][0], acc[jj][1]);
            hc[2 * jj + 1] = h2pack(acc[jj][2], acc[jj][3]);
        }
    };

    // ---------------- race-free pipelined conv (R13 ordering) ----------------
    issueB(0, 0);
    ldx(0);
    cvtA(0);

    #pragma unroll
    for (int g = 0; g < G; g++) {
        __syncthreads();                   // mma(g-1) done -> buf (g+1)&1 free
        if (g < G - 1) {
            issueB(g + 1, (g + 1) & 1);
            cp_wait<1>();                  // B(g) landed
        } else {
            cp_wait<0>();
        }
        __syncthreads();                   // B(g)+cvtA(g) visible to all
        if (g < G - 1) ldx(g + 1);
        mma_group(g, hcon[g]);
        if (g < G - 1) cvtA((g + 1) & 1);
    }
    __syncthreads();

    // ---------------- Gram routing epilogue (register con + smem exchange) ---
    {
        float Gm[36];
        #pragma unroll
        for (int p2 = 0; p2 < 2; p2++) {
            #pragma unroll
            for (int k = 0; k < 36; k++) Gm[k] = 0.f;
            #pragma unroll
            for (int jj = 0; jj < 4; jj++) {
                float2 cc[G];
                #pragma unroll
                for (int g = 0; g < G; g++) cc[g] = h2unpack(hcon[g][2 * jj + p2]);
                #pragma unroll
                for (int kk = 0; kk < 2; kk++) {
                    float c[G];
                    #pragma unroll
                    for (int g = 0; g < G; g++) c[g] = kk ? cc[g].y : cc[g].x;
                    int idx = 0;
                    #pragma unroll
                    for (int g = 0; g < G; g++)
                        #pragma unroll
                        for (int h = g; h < G; h++) {
                            Gm[idx] = fmaf(c[g], c[h], Gm[idx]);
                            idx++;
                        }
                }
            }
            // reduce over the 4 tig lanes (same pixel within warp)
            #pragma unroll
            for (int k = 0; k < 36; k++) {
                Gm[k] += __shfl_xor_sync(0xFFFFFFFFu, Gm[k], 1);
                Gm[k] += __shfl_xor_sync(0xFFFFFFFFu, Gm[k], 2);
            }
            // write this o-half's partial Gram: sgram[slot][px][.]
            const int px = pb + gr + 8 * p2;
            float* dst = sgram + (slot * 64 + px) * 36;
            #pragma unroll
            for (int i = 0; i < 9; i++) dst[tig + 4 * i] = Gm[tig + 4 * i];
        }
        __syncthreads();

        // per-pixel routing iterations (sum both o-half Grams)
        float al[2][G];
        #pragma unroll
        for (int p2 = 0; p2 < 2; p2++) {
            const int px = pb + gr + 8 * p2;
            const float* s0 = sgram + px * 36;
            const float* s1 = sgram + (64 + px) * 36;
            #pragma unroll
            for (int k = 0; k < 36; k++) Gm[k] = s0[k] + s1[k];

            float beta[G];
            #pragma unroll
            for (int g = 0; g < G; g++) beta[g] = 0.f;
            #pragma unroll
            for (int it = 0; it < 2; it++) {
                float a_[G], d[G];
                #pragma unroll
                for (int g = 0; g < G; g++) { a_[g] = sigmoidf(beta[g]); d[g] = 0.f; }
                #pragma unroll
                for (int g = 0; g < G; g++) {
                    #pragma unroll
                    for (int h = 0; h < G; h++) {
                        const int lo2 = g < h ? g : h;
                        const int hi2 = g < h ? h : g;
                        const int idx = lo2 * G - (lo2 * (lo2 - 1)) / 2 + (hi2 - lo2);
                        d[g] = fmaf(a_[h], Gm[idx], d[g]);
                    }
                }
                #pragma unroll
                for (int g = 0; g < G; g++) beta[g] += d[g];
            }
            #pragma unroll
            for (int g = 0; g < G; g++) al[p2][g] = sigmoidf(beta[g]);
        }

        // final combine from registers + bias + store
        float* ob2 = out + (size_t)b * FO * HW + p0;
        #pragma unroll
        for (int jj = 0; jj < 4; jj++) {
            const int o0 = ob + 8 * jj + 2 * tig;
            const float b0 = __ldg(bias + o0);
            const float b1 = __ldg(bias + o0 + 1);
            #pragma unroll
            for (int p2 = 0; p2 < 2; p2++) {
                const int px = pb + gr + 8 * p2;
                float v0 = 0.f, v1 = 0.f;
                #pragma unroll
                for (int g = 0; g < G; g++) {
                    float2 cc = h2unpack(hcon[g][2 * jj + p2]);
                    v0 = fmaf(al[p2][g], cc.x, v0);
                    v1 = fmaf(al[p2][g], cc.y, v1);
                }
                ob2[(size_t)o0       * HW + px] = v0 + b0;
                ob2[(size_t)(o0 + 1) * HW + px] = v1 + b1;
            }
        }
    }
}

extern "C" void kernel_launch(void* const* d_in, const int* in_sizes, int n_in,
                              void* d_out, int out_size)
{
    const float* x    = (const float*)d_in[0];
    const float* wgt  = (const float*)d_in[1];
    const float* bias = (const float*)d_in[2];
    float* out        = (float*)d_out;

    static int attr_set = 0;
    if (!attr_set) {
        cudaFuncSetAttribute(dynrout_hmma,
                             cudaFuncAttributeMaxDynamicSharedMemorySize, SMEM_TOTAL);
        attr_set = 1;
    }

    pack_w_kernel<<<64, 256>>>(wgt);
    dim3 grid(BSZ * (HW / TP));            // 2048
    dynrout_hmma<<<grid, NTHREADS, SMEM_TOTAL>>>(x, bias, out);
}

// round 17
// speedup vs baseline: 1.7204x; 1.7204x over previous
#include <cuda_runtime.h>
#include <cuda_fp16.h>
#include <cstdint>
#include <cstring>

// DynamicRouting: grouped 1x1 conv via single-pass fp16 mma.sync (fp32 accum).
// con stored in smem as half2 o-pairs (66KB), total smem 100KB -> 2 CTAs/SM.
// Register-only Gram routing epilogue reading packed con.

#define G   8
#define FO  64
#define FI  64
#define HW  4096
#define C   512
#define BSZ 32
#define TP  64
#define NTHREADS 256

// con2: [G][32 o-pairs][stride 66] uint32 (half2), bank-engineered
#define OPSTR 66
#define CONG2 (32*OPSTR)               // 2112 words per group
#define OFF_BUF (G*CONG2*4)            // 67584 B
#define BUFSZ   16384                  // [A 8K | B 8K] fp16 tiles
#define AOF 0
#define BOF 8192
#define SMEM_TOTAL (OFF_BUF + 2*BUFSZ) // 100352 B

// packed weights: per group 8KB fp16, swizzled B-tile layout
__device__ __align__(16) unsigned char g_wpack[G * 8192];

__device__ __forceinline__ uint32_t swz(uint32_t off) {
    return off ^ ((off >> 3) & 0x70);
}
__device__ __forceinline__ uint32_t s2u(const void* p) {
    return (uint32_t)__cvta_generic_to_shared(p);
}
__device__ __forceinline__ void cp16(uint32_t d, const void* s) {
    asm volatile("cp.async.cg.shared.global [%0], [%1], 16;\n" :: "r"(d), "l"(s));
}
__device__ __forceinline__ void cp_commit() {
    asm volatile("cp.async.commit_group;\n");
}
template <int N>
__device__ __forceinline__ void cp_wait() {
    asm volatile("cp.async.wait_group %0;\n" :: "n"(N));
}
__device__ __forceinline__ uint32_t h2pack(float v0, float v1) {
    __half2 h = __floats2half2_rn(v0, v1);
    uint32_t r; memcpy(&r, &h, 4); return r;
}
__device__ __forceinline__ float2 h2unpack(uint32_t u) {
    __half2 h; memcpy(&h, &u, 4);
    return __half22float2(h);
}
__device__ __forceinline__ void mma16816(float* d,
    uint32_t a0, uint32_t a1, uint32_t a2, uint32_t a3, uint32_t b0, uint32_t b1)
{
    asm volatile("mma.sync.aligned.m16n8k16.row.col.f32.f16.f16.f32 "
        "{%0,%1,%2,%3}, {%4,%5,%6,%7}, {%8,%9}, {%0,%1,%2,%3};"
        : "+f"(d[0]), "+f"(d[1]), "+f"(d[2]), "+f"(d[3])
        : "r"(a0), "r"(a1), "r"(a2), "r"(a3), "r"(b0), "r"(b1));
}
__device__ __forceinline__ float sigmoidf(float b) {
    return 1.f / (1.f + __expf(-b));
}
__device__ __forceinline__ uint32_t lds32(const char* p) {
    return *(const uint32_t*)p;
}

// ---- pre-kernel: w fp32 [g][o][i] -> fp16 swizzled B tiles ----
__global__ void pack_w_kernel(const float* __restrict__ w) {
    int f = blockIdx.x * blockDim.x + threadIdx.x;   // 0..16383 (word pairs)
    int g = f >> 11, rem = f & 2047;
    int o = rem >> 5, iw = rem & 31;                 // i = 2*iw
    const float* src = w + (((size_t)g * FO + o) * FI + 2 * iw);
    uint32_t hv = h2pack(src[0], src[1]);
    uint32_t boff = swz((uint32_t)(o * 128 + iw * 4));
    *(uint32_t*)(g_wpack + g * 8192 + boff) = hv;
}

__global__ __launch_bounds__(NTHREADS, 2)
void dynrout_hmma(const float* __restrict__ x, const float* __restrict__ bias,
                  float* __restrict__ out)
{
    extern __shared__ char smem[];
    uint32_t* con2 = (uint32_t*)smem;      // [G][32][OPSTR] half2

    const int tid = threadIdx.x;
    const int wid = tid >> 5, lid = tid & 31;
    const int b   = blockIdx.x >> 6;
    const int p0  = (blockIdx.x & 63) << 6;

    // producer roles (all 256 threads)
    const int xpx = tid & 63;
    const int xi0 = (tid >> 6) << 4;

    // mma roles: 8 warps, m16 x n32 tiles
    const int gr = lid >> 2, tig = lid & 3;
    const int pb = (wid & 3) << 4;          // px tile base
    const int ob = (wid >> 2) << 5;         // o tile base (32 o's)

    const float* xbase = x + (size_t)b * C * HW + p0;
    float xr[16];

    auto ldx = [&](int g) {
        const float* xp = xbase + (size_t)g * FI * HW + xpx;
        #pragma unroll
        for (int k = 0; k < 16; k++) xr[k] = __ldg(xp + (size_t)(xi0 + k) * HW);
    };
    auto issueB = [&](int g, int buf) {      // 8KB coalesced fp16 tile
        const unsigned char* src = g_wpack + g * 8192;
        uint32_t d0 = s2u(smem + OFF_BUF + buf * BUFSZ + BOF);
        #pragma unroll
        for (int r = 0; r < 2; r++)
            cp16(d0 + (uint32_t)(r * 4096 + tid * 16), src + r * 4096 + tid * 16);
        cp_commit();
    };
    auto cvtA = [&](int buf) {
        char* bp = smem + OFF_BUF + buf * BUFSZ;
        uint32_t hv[8];
        #pragma unroll
        for (int k = 0; k < 8; k++) hv[k] = h2pack(xr[2*k], xr[2*k+1]);
        uint32_t offA = (uint32_t)(xpx * 128 + xi0 * 2);
        *(uint4*)(bp + AOF + swz(offA))    = make_uint4(hv[0], hv[1], hv[2], hv[3]);
        *(uint4*)(bp + AOF + swz(offA+16)) = make_uint4(hv[4], hv[5], hv[6], hv[7]);
    };

    auto mma_group = [&](int g) {
        const char* bp = smem + OFF_BUF + (g & 1) * BUFSZ;
        float acc[4][4];
        #pragma unroll
        for (int j = 0; j < 4; j++)
            #pragma unroll
            for (int k = 0; k < 4; k++) acc[j][k] = 0.f;

        #pragma unroll
        for (int ks = 0; ks < 4; ks++) {
            uint32_t r0 = (uint32_t)((pb + gr)     * 128 + tig * 4 + ks * 32);
            uint32_t r1 = (uint32_t)((pb + gr + 8) * 128 + tig * 4 + ks * 32);
            uint32_t a0 = lds32(bp + AOF + swz(r0));
            uint32_t a1 = lds32(bp + AOF + swz(r1));
            uint32_t a2 = lds32(bp + AOF + swz(r0 + 16));
            uint32_t a3 = lds32(bp + AOF + swz(r1 + 16));
            #pragma unroll
            for (int jj = 0; jj < 4; jj++) {
                uint32_t rb = (uint32_t)((ob + 8 * jj + gr) * 128 + tig * 4 + ks * 32);
                uint32_t b0 = lds32(bp + BOF + swz(rb));
                uint32_t b1 = lds32(bp + BOF + swz(rb + 16));
                mma16816(acc[jj], a0, a1, a2, a3, b0, b1);
            }
        }
        // store con as half2 o-pairs: row op = o/2, px column
        uint32_t* cg = con2 + g * CONG2;
        const int px0 = pb + gr;
        #pragma unroll
        for (int jj = 0; jj < 4; jj++) {
            const int opr = (ob >> 1) + 4 * jj + tig;
            cg[opr * OPSTR + px0]     = h2pack(acc[jj][0], acc[jj][1]);
            cg[opr * OPSTR + px0 + 8] = h2pack(acc[jj][2], acc[jj][3]);
        }
    };

    // ---------------- race-free pipelined conv (R13/R15 ordering) -----------
    issueB(0, 0);
    ldx(0);
    cvtA(0);

    for (int g = 0; g < G; g++) {
        __syncthreads();                   // mma(g-1) done -> buf (g+1)&1 free
        if (g < G - 1) {
            issueB(g + 1, (g + 1) & 1);
            cp_wait<1>();                  // B(g) landed
        } else {
            cp_wait<0>();
        }
        __syncthreads();                   // B(g)+cvtA(g) visible to all
        if (g < G - 1) ldx(g + 1);
        mma_group(g);
        if (g < G - 1) cvtA((g + 1) & 1);
    }
    __syncthreads();

    // -------- Gram routing epilogue: 256 thr = 64 px x 4 o-lanes -----------
    {
        const int p  = tid >> 2;           // pixel
        const int oq = tid & 3;            // o-partition lane
        const uint32_t* conp = con2 + p;
        // o-pair op(j) = 4*oq + (j&3) + 16*(j>>2); word bank = (2*op + p)%32
        //  = (8*oq + lane_p + const)%32 -> conflict-free

        float Gm[36];
        #pragma unroll
        for (int k = 0; k < 36; k++) Gm[k] = 0.f;

        #pragma unroll
        for (int j = 0; j < 8; j++) {
            const int op = 4 * oq + (j & 3) + 16 * (j >> 2);
            float2 cc[G];
            #pragma unroll
            for (int g = 0; g < G; g++)
                cc[g] = h2unpack(conp[g * CONG2 + op * OPSTR]);
            #pragma unroll
            for (int kk = 0; kk < 2; kk++) {
                float c[G];
                #pragma unroll
                for (int g = 0; g < G; g++) c[g] = kk ? cc[g].y : cc[g].x;
                int idx = 0;
                #pragma unroll
                for (int g = 0; g < G; g++)
                    #pragma unroll
                    for (int h = g; h < G; h++) {
                        Gm[idx] = fmaf(c[g], c[h], Gm[idx]);
                        idx++;
                    }
            }
        }
        // reduce Gram over the 4 same-pixel lanes
        #pragma unroll
        for (int k = 0; k < 36; k++) {
            Gm[k] += __shfl_xor_sync(0xFFFFFFFFu, Gm[k], 1);
            Gm[k] += __shfl_xor_sync(0xFFFFFFFFu, Gm[k], 2);
        }

        // register-only routing iterations
        float beta[G];
        #pragma unroll
        for (int g = 0; g < G; g++) beta[g] = 0.f;
        #pragma unroll
        for (int it = 0; it < 2; it++) {
            float al[G], d[G];
            #pragma unroll
            for (int g = 0; g < G; g++) { al[g] = sigmoidf(beta[g]); d[g] = 0.f; }
            #pragma unroll
            for (int g = 0; g < G; g++) {
                #pragma unroll
                for (int h = 0; h < G; h++) {
                    const int lo2 = g < h ? g : h;
                    const int hi2 = g < h ? h : g;
                    const int idx = lo2 * G - (lo2 * (lo2 - 1)) / 2 + (hi2 - lo2);
                    d[g] = fmaf(al[h], Gm[idx], d[g]);
                }
            }
            #pragma unroll
            for (int g = 0; g < G; g++) beta[g] += d[g];
        }
        float al[G];
        #pragma unroll
        for (int g = 0; g < G; g++) al[g] = sigmoidf(beta[g]);

        // final combine + bias + store
        float* ob2 = out + (size_t)b * FO * HW + p0 + p;
        #pragma unroll
        for (int j = 0; j < 8; j++) {
            const int op = 4 * oq + (j & 3) + 16 * (j >> 2);
            const int o0 = 2 * op;
            float v0 = 0.f, v1 = 0.f;
            #pragma unroll
            for (int g = 0; g < G; g++) {
                float2 cc = h2unpack(conp[g * CONG2 + op * OPSTR]);
                v0 = fmaf(al[g], cc.x, v0);
                v1 = fmaf(al[g], cc.y, v1);
            }
            ob2[(size_t)o0       * HW] = v0 + __ldg(bias + o0);
            ob2[(size_t)(o0 + 1) * HW] = v1 + __ldg(bias + o0 + 1);
        }
    }
}

extern "C" void kernel_launch(void* const* d_in, const int* in_sizes, int n_in,
                              void* d_out, int out_size)
{
    const float* x    = (const float*)d_in[0];
    const float* wgt  = (const float*)d_in[1];
    const float* bias = (const float*)d_in[2];
    float* out        = (float*)d_out;

    static int attr_set = 0;
    if (!attr_set) {
        cudaFuncSetAttribute(dynrout_hmma,
                             cudaFuncAttributeMaxDynamicSharedMemorySize, SMEM_TOTAL);
        attr_set = 1;
    }

    pack_w_kernel<<<64, 256>>>(wgt);
    dim3 grid(BSZ * (HW / TP));            // 2048
    dynrout_hmma<<<grid, NTHREADS, SMEM_TOTAL>>>(x, bias, out);
}